// round 7
// baseline (speedup 1.0000x reference)
#include <cuda_runtime.h>
#include <cuda_bf16.h>
#include <cstdint>

// ---------------------------------------------------------------------------
// Fused two-tower scorer, round 7: 64x256 tiles, 256 CTAs, 256 thr, 2 CTAs/SM.
// W double-buffered cp.async, A LDG->cvt.rna->STS (permuted, LDS.128 frags),
// user latent kept in packed bf16x2 registers (no smem round-trip).
// (R6 with the nonexistent bfloat162 bit-cast intrinsics replaced by native
//  __nv_bfloat162 register storage.)
// ---------------------------------------------------------------------------

#define NTHREADS 256
#define TB       64      // batch rows per CTA
#define LOUT     256     // latents (GEMM N)
#define KF       512     // features (GEMM K)
#define KC       32      // K chunk (floats)
#define NCHUNK   32      // 16 chunks/tower x 2 towers
#define AST      36      // A smem row stride (floats), conflict-free
#define WST      36      // W smem row stride (floats), conflict-free

// smem byte offsets
#define S_IDXU   0                       // 64 ints
#define S_IDXI   256
#define S_UB     512                     // 256 f32
#define S_IB     1536
#define S_PART   2560                    // 64 f32
#define S_A      4096                    // A tiles, double buffered
#define A_BYTES  (TB * AST * 4)          // 9216
#define S_W      (S_A + 2 * A_BYTES)     // 22528, W double buffered
#define W_BYTES  (LOUT * WST * 4)        // 36864
#define S_TOTAL  (S_W + 2 * W_BYTES)     // 96256  -> 2 CTAs/SM

// pre-rounded, permuted weights: [tower][l][512], k=4j+t stored at t*8+j
__device__ float wscr[2 * LOUT * KF];

// --------------------------- helpers ----------------------------------------

__device__ __forceinline__ float tf32f(float x) {
    uint32_t u;
    asm("cvt.rna.tf32.f32 %0, %1;" : "=r"(u) : "f"(x));
    return __uint_as_float(u);
}

__device__ __forceinline__ void mma8(float* c, uint32_t a0, uint32_t a1,
                                     uint32_t a2, uint32_t a3,
                                     uint32_t b0, uint32_t b1) {
    asm volatile(
        "mma.sync.aligned.m16n8k8.row.col.f32.tf32.tf32.f32 "
        "{%0,%1,%2,%3}, {%4,%5,%6,%7}, {%8,%9}, {%0,%1,%2,%3};"
        : "+f"(c[0]), "+f"(c[1]), "+f"(c[2]), "+f"(c[3])
        : "r"(a0), "r"(a1), "r"(a2), "r"(a3), "r"(b0), "r"(b1));
}

__device__ __forceinline__ void cp16(uint32_t dst, const float* src) {
    asm volatile("cp.async.cg.shared.global [%0], [%1], 16;"
                 :: "r"(dst), "l"(src) : "memory");
}

// W chunk c -> smem buffer c&1 (scratch already rounded + permuted)
__device__ __forceinline__ void issue_w(int c, uint32_t sb, int tid) {
    const int tower = c >> 4, ch = c & 15, buf = c & 1;
    const float* src0 = wscr + tower * (LOUT * KF) + ch * KC;
    const uint32_t dst0 = sb + S_W + buf * W_BYTES;
#pragma unroll
    for (int i = 0; i < 8; i++) {            // 2048 16B segments / 256 thr
        int seg = tid + i * NTHREADS;
        int row = seg >> 3, q = seg & 7;
        cp16(dst0 + row * (WST * 4) + q * 16, src0 + row * KF + q * 4);
    }
    asm volatile("cp.async.commit_group;" ::: "memory");
}

__device__ __forceinline__ void ldg_a(float4* pref, const float* lut,
                                      const int* idx, int kc, int tid) {
#pragma unroll
    for (int i = 0; i < 2; i++) {            // 512 16B segments / 256 thr
        int seg = tid + i * NTHREADS;
        int row = seg >> 3, q = seg & 7;
        pref[i] = __ldg(reinterpret_cast<const float4*>(
            lut + (size_t)idx[row] * KF + kc + q * 4));
    }
}

// store A chunk with rna rounding + permutation: k=4j+t -> pos t*8+j
__device__ __forceinline__ void sts_a(const float4* pref, char* smem, int c,
                                      int tid) {
    float* base = (float*)(smem + S_A + (c & 1) * A_BYTES);
#pragma unroll
    for (int i = 0; i < 2; i++) {
        int seg = tid + i * NTHREADS;
        int row = seg >> 3, q = seg & 7;
        float* rp = base + row * AST + q;
        rp[0]  = tf32f(pref[i].x);
        rp[8]  = tf32f(pref[i].y);
        rp[16] = tf32f(pref[i].z);
        rp[24] = tf32f(pref[i].w);
    }
}

// --------------------------- prep kernel ------------------------------------

__global__ void prep_kernel(const float* __restrict__ uW,
                            const float* __restrict__ iW) {
    int o = blockIdx.x * 256 + threadIdx.x;        // [0, 262144)
    int tower = o >> 17;
    int l = (o >> 9) & (LOUT - 1);
    int p = o & (KF - 1);
    int ch = p >> 5, t = (p >> 3) & 3, j = p & 7;
    const float* W = tower ? iW : uW;
    wscr[o] = tf32f(W[l * KF + ch * KC + 4 * j + t]);
}

// --------------------------- main kernel ------------------------------------

__global__ void __launch_bounds__(NTHREADS, 2) towers_kernel(
    const int* __restrict__ x,
    const float* __restrict__ ulut, const float* __restrict__ ilut,
    const float* __restrict__ ubias, const float* __restrict__ ibias,
    float* __restrict__ out) {
    extern __shared__ char smem[];
    uint32_t sb;
    asm("{ .reg .u64 t; cvta.to.shared.u64 t, %1; cvt.u32.u64 %0, t; }"
        : "=r"(sb) : "l"(smem));
    const int tid  = threadIdx.x;
    const int lane = tid & 31;
    const int wid  = tid >> 5;
    const int wm   = wid & 1;        // 2 row groups of 32
    const int wn   = wid >> 1;       // 4 col groups of 64
    const int g    = lane >> 2;
    const int t    = lane & 3;

    int*   idxu = (int*)(smem + S_IDXU);
    int*   idxi = (int*)(smem + S_IDXI);
    float* ubS  = (float*)(smem + S_UB);
    float* ibS  = (float*)(smem + S_IB);
    float* part = (float*)(smem + S_PART);

    ubS[tid] = ubias[tid];
    ibS[tid] = ibias[tid];
    if (tid < TB) {
        part[tid] = 0.f;
        int gg = blockIdx.x * TB + tid;
        idxu[tid] = x[2 * gg];
        idxi[tid] = x[2 * gg + 1];
    }
    __syncthreads();

    issue_w(0, sb, tid);

    float4 pref[2];
    ldg_a(pref, ulut, idxu, 0, tid);

    float acc[2][8][4];
#pragma unroll
    for (int mt = 0; mt < 2; mt++)
#pragma unroll
        for (int nt = 0; nt < 8; nt++)
#pragma unroll
            for (int i = 0; i < 4; i++) acc[mt][nt][i] = 0.f;

    __nv_bfloat162 upk[2][8][2];     // packed bf16x2 user latents (regs)

    for (int c = 0; c < NCHUNK; c++) {
        // 1. store prefetched A; buffer (c&1) free: last reader MMA(c-2)
        //    is CTA-wide complete past sync(c-1).
        sts_a(pref, smem, c, tid);

        // 2. prefetch next A chunk into regs (latency hidden under MMA)
        if (c + 1 < NCHUNK) {
            int c2 = c + 1;
            bool t2 = (c2 >= NCHUNK / 2);
            ldg_a(pref, t2 ? ilut : ulut, t2 ? idxi : idxu,
                  (c2 & 15) * KC, tid);
        }

        // 3. W chunk c arrived (only group c outstanding here)
        asm volatile("cp.async.wait_group 0;" ::: "memory");
        __syncthreads();

        // 4. refill W buffer (c+1)&1: last reader MMA(c-1) done pre-sync
        if (c + 1 < NCHUNK) issue_w(c + 1, sb, tid);

        // 5. MMA on chunk c
        const float* A  = (const float*)(smem + S_A + (c & 1) * A_BYTES);
        const float* Bs = (const float*)(smem + S_W + (c & 1) * W_BYTES);
#pragma unroll
        for (int h = 0; h < 2; h++) {        // two k-step pairs
            float4 alo[2], ahi[2];
#pragma unroll
            for (int mt = 0; mt < 2; mt++) {
                const int r0 = wm * 32 + mt * 16 + g;
                alo[mt] = *(const float4*)(A + r0 * AST + t * 8 + h * 4);
                ahi[mt] = *(const float4*)(A + (r0 + 8) * AST + t * 8 + h * 4);
            }
#pragma unroll
            for (int ntb = 0; ntb < 2; ntb++) {
                float4 bv[4];
#pragma unroll
                for (int n4 = 0; n4 < 4; n4++) {
                    const int n0 = wn * 64 + (ntb * 4 + n4) * 8 + g;
                    bv[n4] = *(const float4*)(Bs + n0 * WST + t * 8 + h * 4);
                }
#pragma unroll
                for (int sp = 0; sp < 2; sp++) {
#pragma unroll
                    for (int mt = 0; mt < 2; mt++) {
                        const float* al = (const float*)&alo[mt];
                        const float* ah = (const float*)&ahi[mt];
                        uint32_t a0 = __float_as_uint(al[2 * sp]);
                        uint32_t a1 = __float_as_uint(ah[2 * sp]);
                        uint32_t a2 = __float_as_uint(al[2 * sp + 1]);
                        uint32_t a3 = __float_as_uint(ah[2 * sp + 1]);
#pragma unroll
                        for (int n4 = 0; n4 < 4; n4++) {
                            const float* bp = (const float*)&bv[n4];
                            mma8(acc[mt][ntb * 4 + n4],
                                 a0, a1, a2, a3,
                                 __float_as_uint(bp[2 * sp]),
                                 __float_as_uint(bp[2 * sp + 1]));
                        }
                    }
                }
            }
        }

        // 6. user-tower epilogue: bias + relu -> packed bf16x2 regs
        if (c == NCHUNK / 2 - 1) {
#pragma unroll
            for (int mt = 0; mt < 2; mt++) {
#pragma unroll
                for (int nt = 0; nt < 8; nt++) {
                    const int c0 = wn * 64 + nt * 8 + 2 * t;
                    float u0 = fmaxf(acc[mt][nt][0] + ubS[c0],     0.f);
                    float u1 = fmaxf(acc[mt][nt][1] + ubS[c0 + 1], 0.f);
                    float u2 = fmaxf(acc[mt][nt][2] + ubS[c0],     0.f);
                    float u3 = fmaxf(acc[mt][nt][3] + ubS[c0 + 1], 0.f);
                    upk[mt][nt][0] = __floats2bfloat162_rn(u0, u1);
                    upk[mt][nt][1] = __floats2bfloat162_rn(u2, u3);
                    acc[mt][nt][0] = acc[mt][nt][1] = 0.f;
                    acc[mt][nt][2] = acc[mt][nt][3] = 0.f;
                }
            }
        }
    }

    // item-tower epilogue: bias+relu, product with packed user latent, reduce
#pragma unroll
    for (int mt = 0; mt < 2; mt++) {
        const int r0 = wm * 32 + mt * 16 + g;
        float s0 = 0.f, s1 = 0.f;
#pragma unroll
        for (int nt = 0; nt < 8; nt++) {
            const int c0 = wn * 64 + nt * 8 + 2 * t;
            float v0 = fmaxf(acc[mt][nt][0] + ibS[c0],     0.f);
            float v1 = fmaxf(acc[mt][nt][1] + ibS[c0 + 1], 0.f);
            float v2 = fmaxf(acc[mt][nt][2] + ibS[c0],     0.f);
            float v3 = fmaxf(acc[mt][nt][3] + ibS[c0 + 1], 0.f);
            float2 u01 = __bfloat1622float2(upk[mt][nt][0]);
            float2 u23 = __bfloat1622float2(upk[mt][nt][1]);
            s0 = fmaf(u01.x, v0, fmaf(u01.y, v1, s0));
            s1 = fmaf(u23.x, v2, fmaf(u23.y, v3, s1));
        }
        s0 += __shfl_xor_sync(0xffffffffu, s0, 1);
        s0 += __shfl_xor_sync(0xffffffffu, s0, 2);
        s1 += __shfl_xor_sync(0xffffffffu, s1, 1);
        s1 += __shfl_xor_sync(0xffffffffu, s1, 2);
        if (t == 0) {
            atomicAdd(&part[r0], s0);
            atomicAdd(&part[r0 + 8], s1);
        }
    }
    __syncthreads();

    if (tid < TB) out[blockIdx.x * TB + tid] = part[tid];
}

// --------------------------- launch -----------------------------------------

extern "C" void kernel_launch(void* const* d_in, const int* in_sizes, int n_in,
                              void* d_out, int out_size) {
    const int* x      = (const int*)d_in[0];
    const float* ulut = (const float*)d_in[1];
    const float* ilut = (const float*)d_in[2];
    const float* uW   = (const float*)d_in[3];
    const float* ub   = (const float*)d_in[4];
    const float* iW   = (const float*)d_in[5];
    const float* ib   = (const float*)d_in[6];
    float* out        = (float*)d_out;

    prep_kernel<<<2 * LOUT * KF / 256, 256>>>(uW, iW);

    cudaFuncSetAttribute(towers_kernel,
                         cudaFuncAttributeMaxDynamicSharedMemorySize, S_TOTAL);
    int grid = out_size / TB;   // 16384 / 64 = 256
    towers_kernel<<<grid, NTHREADS, S_TOTAL>>>(x, ulut, ilut, ub, ib, out);
}

// round 8
// speedup vs baseline: 1.0229x; 1.0229x over previous
#include <cuda_runtime.h>
#include <cuda_fp16.h>
#include <cstdint>

// ---------------------------------------------------------------------------
// Fused two-tower scorer, round 8: fp16 m16n8k16 MMA (same 10-bit mantissa as
// tf32, fp32 accumulate). Operand bytes and MMA count halve vs tf32; K-chunk
// 64 halves barrier count. 128 CTAs x 512 thr, tile 128x256, warp tile 32x64.
// A: LDG.128 -> cvt fp16 -> STS (pair-permuted, LDS.128 frags). W: prep kernel
// pre-converts + permutes to fp16 pairs; cp.async triple-buffered.
// ---------------------------------------------------------------------------

#define NTHREADS 512
#define TB       128     // batch rows per CTA
#define LOUT     256     // latents (GEMM N)
#define KF       512     // features (GEMM K)
#define KC       64      // K chunk (elements); 32 fp16-pairs per row
#define NCHUNK   16      // 8 chunks per tower x 2 towers
#define ASTU     36      // A smem row stride (uint pairs), conflict-free
#define WSTU     36      // W smem row stride (uint pairs)
#define ULST     264     // user-latent smem stride (halves)

// smem byte offsets
#define S_IDXU   0                       // 128 ints
#define S_IDXI   512
#define S_UB     1024                    // 256 f32
#define S_IB     2048
#define S_PART   3072                    // 128 f32
#define S_ULAT   3584                    // 128 x 264 half = 67584
#define S_A      71168                   // A tiles, double buffered
#define A_BYTES  (TB * ASTU * 4)         // 18432
#define S_W      (S_A + 2 * A_BYTES)     // 108032, W triple buffered
#define W_BYTES  (LOUT * WSTU * 4)       // 36864
#define S_TOTAL  (S_W + 3 * W_BYTES)     // 218624  (1 CTA/SM)

// pre-converted, pair-permuted fp16 weights:
// uint index = tower*65536 + l*256 + ch*32 + pos, pos = t*8 + s*2 + m
// holds W[l][ch*64 + 2p .. +1] as half2, where p = 8s + 4m + t.
__device__ uint32_t wscr[2 * LOUT * 256];

// --------------------------- helpers ----------------------------------------

__device__ __forceinline__ void mma16(float* c, uint32_t a0, uint32_t a1,
                                      uint32_t a2, uint32_t a3,
                                      uint32_t b0, uint32_t b1) {
    asm volatile(
        "mma.sync.aligned.m16n8k16.row.col.f32.f16.f16.f32 "
        "{%0,%1,%2,%3}, {%4,%5,%6,%7}, {%8,%9}, {%0,%1,%2,%3};"
        : "+f"(c[0]), "+f"(c[1]), "+f"(c[2]), "+f"(c[3])
        : "r"(a0), "r"(a1), "r"(a2), "r"(a3), "r"(b0), "r"(b1));
}

__device__ __forceinline__ void cp16(uint32_t dst, const void* src) {
    asm volatile("cp.async.cg.shared.global [%0], [%1], 16;"
                 :: "r"(dst), "l"(src) : "memory");
}

__device__ __forceinline__ uint32_t h2u(__half2 h) {
    return *reinterpret_cast<uint32_t*>(&h);
}

// W chunk c -> smem buffer c%3 (scratch already fp16 + permuted)
__device__ __forceinline__ void issue_w(int c, uint32_t sb, int tid) {
    const int tower = c >> 3, ch = c & 7, buf = c % 3;
    const uint32_t* src0 = wscr + tower * 65536 + ch * 32;
    const uint32_t dst0 = sb + S_W + buf * W_BYTES;
#pragma unroll
    for (int i = 0; i < 4; i++) {            // 2048 16B segs / 512 thr
        int seg = tid + i * NTHREADS;
        int row = seg >> 3, q = seg & 7;     // 8 segs per 32-uint row
        cp16(dst0 + row * (WSTU * 4) + q * 16, src0 + row * 256 + q * 4);
    }
    asm volatile("cp.async.commit_group;" ::: "memory");
}

// A chunk: 128 rows x 16 float4 = 2048 segs / 512 thr = 4 per thread
__device__ __forceinline__ void ldg_a(float4* pref, const float* lut,
                                      const int* idx, int kc, int tid) {
#pragma unroll
    for (int i = 0; i < 4; i++) {
        int seg = tid + i * NTHREADS;
        int row = seg >> 4, q = seg & 15;
        pref[i] = __ldg(reinterpret_cast<const float4*>(
            lut + (size_t)idx[row] * KF + kc + q * 4));
    }
}

// store A chunk as fp16 pairs with permutation:
// pair p (k=2p,2p+1) -> pos = (p&3)*8 + (p>>3)*2 + ((p>>2)&1)
__device__ __forceinline__ void sts_a(const float4* pref, char* smem, int c,
                                      int tid) {
    uint32_t* base = (uint32_t*)(smem + S_A + (c & 1) * A_BYTES);
#pragma unroll
    for (int i = 0; i < 4; i++) {
        int seg = tid + i * NTHREADS;
        int row = seg >> 4, q = seg & 15;
        int p1 = 2 * q, p2 = 2 * q + 1;
        int pos1 = (p1 & 3) * 8 + (p1 >> 3) * 2 + ((p1 >> 2) & 1);
        int pos2 = (p2 & 3) * 8 + (p2 >> 3) * 2 + ((p2 >> 2) & 1);
        base[row * ASTU + pos1] = h2u(__floats2half2_rn(pref[i].x, pref[i].y));
        base[row * ASTU + pos2] = h2u(__floats2half2_rn(pref[i].z, pref[i].w));
    }
}

// --------------------------- prep kernel ------------------------------------

__global__ void prep_kernel(const float* __restrict__ uW,
                            const float* __restrict__ iW) {
    int o = blockIdx.x * 256 + threadIdx.x;        // [0, 131072)
    int tower = o >> 16;
    int l = (o >> 8) & (LOUT - 1);
    int r = o & 255;
    int ch = r >> 5, pos = r & 31;
    int t = pos >> 3, q = pos & 7, s = q >> 1, m = q & 1;
    int p = 8 * s + 4 * m + t;
    const float* W = (tower ? iW : uW) + (size_t)l * KF + ch * KC + 2 * p;
    wscr[o] = h2u(__floats2half2_rn(W[0], W[1]));
}

// --------------------------- main kernel ------------------------------------

__global__ void __launch_bounds__(NTHREADS, 1) towers_kernel(
    const int* __restrict__ x,
    const float* __restrict__ ulut, const float* __restrict__ ilut,
    const float* __restrict__ ubias, const float* __restrict__ ibias,
    float* __restrict__ out) {
    extern __shared__ char smem[];
    uint32_t sb;
    asm("{ .reg .u64 t; cvta.to.shared.u64 t, %1; cvt.u32.u64 %0, t; }"
        : "=r"(sb) : "l"(smem));
    const int tid  = threadIdx.x;
    const int lane = tid & 31;
    const int wid  = tid >> 5;
    const int wm   = wid & 3;        // 4 row groups of 32
    const int wn   = wid >> 2;       // 4 col groups of 64
    const int g    = lane >> 2;
    const int t    = lane & 3;

    int*   idxu = (int*)(smem + S_IDXU);
    int*   idxi = (int*)(smem + S_IDXI);
    float* ubS  = (float*)(smem + S_UB);
    float* ibS  = (float*)(smem + S_IB);
    float* part = (float*)(smem + S_PART);
    __half* ulat = (__half*)(smem + S_ULAT);

    if (tid < LOUT) {
        ubS[tid] = ubias[tid];
        ibS[tid] = ibias[tid];
    }
    if (tid < TB) {
        part[tid] = 0.f;
        int gg = blockIdx.x * TB + tid;
        idxu[tid] = x[2 * gg];
        idxi[tid] = x[2 * gg + 1];
    }
    __syncthreads();

    issue_w(0, sb, tid);
    issue_w(1, sb, tid);

    float4 pref[4];
    ldg_a(pref, ulut, idxu, 0, tid);

    float acc[2][8][4];
#pragma unroll
    for (int mt = 0; mt < 2; mt++)
#pragma unroll
        for (int nt = 0; nt < 8; nt++)
#pragma unroll
            for (int i = 0; i < 4; i++) acc[mt][nt][i] = 0.f;

    for (int c = 0; c < NCHUNK; c++) {
        // 1. store prefetched A; buffer (c&1)'s last reader MMA(c-2) is
        //    CTA-wide complete past sync(c-1).
        sts_a(pref, smem, c, tid);

        // 2. prefetch next A chunk into regs
        if (c + 1 < NCHUNK) {
            int c2 = c + 1;
            bool t2 = (c2 >= NCHUNK / 2);
            ldg_a(pref, t2 ? ilut : ulut, t2 ? idxi : idxu,
                  (c2 & 7) * KC, tid);
        }

        // 3. ensure W chunk c landed (newest outstanding group is c+1)
        if (c <= NCHUNK - 3)
            asm volatile("cp.async.wait_group 1;" ::: "memory");
        else
            asm volatile("cp.async.wait_group 0;" ::: "memory");
        __syncthreads();

        // 4. refill W pipeline
        if (c + 2 < NCHUNK) issue_w(c + 2, sb, tid);

        // 5. MMA on chunk c: 4 k-steps of 16
        const uint32_t* A  =
            (const uint32_t*)(smem + S_A + (c & 1) * A_BYTES);
        const uint32_t* Bs =
            (const uint32_t*)(smem + S_W + (c % 3) * W_BYTES);
#pragma unroll
        for (int h = 0; h < 2; h++) {        // ksteps {2h, 2h+1}
            uint4 alo[2], ahi[2];
#pragma unroll
            for (int mt = 0; mt < 2; mt++) {
                const int r0 = wm * 32 + mt * 16 + g;
                alo[mt] = *(const uint4*)(A + r0 * ASTU + t * 8 + h * 4);
                ahi[mt] = *(const uint4*)(A + (r0 + 8) * ASTU + t * 8 + h * 4);
            }
#pragma unroll
            for (int ntb = 0; ntb < 2; ntb++) {
                uint4 bv[4];
#pragma unroll
                for (int n4 = 0; n4 < 4; n4++) {
                    const int n0 = wn * 64 + (ntb * 4 + n4) * 8 + g;
                    bv[n4] = *(const uint4*)(Bs + n0 * WSTU + t * 8 + h * 4);
                }
#pragma unroll
                for (int si = 0; si < 2; si++) {   // kstep 2h+si
#pragma unroll
                    for (int mt = 0; mt < 2; mt++) {
                        const uint32_t* al = (const uint32_t*)&alo[mt];
                        const uint32_t* ah = (const uint32_t*)&ahi[mt];
                        uint32_t a0 = al[2 * si];
                        uint32_t a1 = ah[2 * si];
                        uint32_t a2 = al[2 * si + 1];
                        uint32_t a3 = ah[2 * si + 1];
#pragma unroll
                        for (int n4 = 0; n4 < 4; n4++) {
                            const uint32_t* bp = (const uint32_t*)&bv[n4];
                            mma16(acc[mt][ntb * 4 + n4],
                                  a0, a1, a2, a3,
                                  bp[2 * si], bp[2 * si + 1]);
                        }
                    }
                }
            }
        }

        // 6. user-tower epilogue: bias + relu -> fp16 smem, reset acc
        if (c == NCHUNK / 2 - 1) {
#pragma unroll
            for (int mt = 0; mt < 2; mt++) {
                const int r0 = wm * 32 + mt * 16 + g;
#pragma unroll
                for (int nt = 0; nt < 8; nt++) {
                    const int c0 = wn * 64 + nt * 8 + 2 * t;
                    float u0 = fmaxf(acc[mt][nt][0] + ubS[c0],     0.f);
                    float u1 = fmaxf(acc[mt][nt][1] + ubS[c0 + 1], 0.f);
                    float u2 = fmaxf(acc[mt][nt][2] + ubS[c0],     0.f);
                    float u3 = fmaxf(acc[mt][nt][3] + ubS[c0 + 1], 0.f);
                    *(__half2*)(ulat + r0 * ULST + c0) =
                        __floats2half2_rn(u0, u1);
                    *(__half2*)(ulat + (r0 + 8) * ULST + c0) =
                        __floats2half2_rn(u2, u3);
                    acc[mt][nt][0] = acc[mt][nt][1] = 0.f;
                    acc[mt][nt][2] = acc[mt][nt][3] = 0.f;
                }
            }
        }
    }

    // item-tower epilogue: bias+relu, product with user latent, row-reduce
#pragma unroll
    for (int mt = 0; mt < 2; mt++) {
        const int r0 = wm * 32 + mt * 16 + g;
        float s0 = 0.f, s1 = 0.f;
#pragma unroll
        for (int nt = 0; nt < 8; nt++) {
            const int c0 = wn * 64 + nt * 8 + 2 * t;
            float v0 = fmaxf(acc[mt][nt][0] + ibS[c0],     0.f);
            float v1 = fmaxf(acc[mt][nt][1] + ibS[c0 + 1], 0.f);
            float v2 = fmaxf(acc[mt][nt][2] + ibS[c0],     0.f);
            float v3 = fmaxf(acc[mt][nt][3] + ibS[c0 + 1], 0.f);
            float2 u01 = __half22float2(*(__half2*)(ulat + r0 * ULST + c0));
            float2 u23 = __half22float2(
                *(__half2*)(ulat + (r0 + 8) * ULST + c0));
            s0 = fmaf(u01.x, v0, fmaf(u01.y, v1, s0));
            s1 = fmaf(u23.x, v2, fmaf(u23.y, v3, s1));
        }
        s0 += __shfl_xor_sync(0xffffffffu, s0, 1);
        s0 += __shfl_xor_sync(0xffffffffu, s0, 2);
        s1 += __shfl_xor_sync(0xffffffffu, s1, 1);
        s1 += __shfl_xor_sync(0xffffffffu, s1, 2);
        if (t == 0) {
            atomicAdd(&part[r0], s0);
            atomicAdd(&part[r0 + 8], s1);
        }
    }
    __syncthreads();

    if (tid < TB) out[blockIdx.x * TB + tid] = part[tid];
}

// --------------------------- launch -----------------------------------------

extern "C" void kernel_launch(void* const* d_in, const int* in_sizes, int n_in,
                              void* d_out, int out_size) {
    const int* x      = (const int*)d_in[0];
    const float* ulut = (const float*)d_in[1];
    const float* ilut = (const float*)d_in[2];
    const float* uW   = (const float*)d_in[3];
    const float* ub   = (const float*)d_in[4];
    const float* iW   = (const float*)d_in[5];
    const float* ib   = (const float*)d_in[6];
    float* out        = (float*)d_out;

    prep_kernel<<<2 * LOUT * 256 / 256, 256>>>(uW, iW);

    cudaFuncSetAttribute(towers_kernel,
                         cudaFuncAttributeMaxDynamicSharedMemorySize, S_TOTAL);
    int grid = out_size / TB;   // 16384 / 128 = 128
    towers_kernel<<<grid, NTHREADS, S_TOTAL>>>(x, ulut, ilut, ub, ib, out);
}

// round 9
// speedup vs baseline: 1.6470x; 1.6101x over previous
#include <cuda_runtime.h>
#include <cuda_fp16.h>
#include <cstdint>

// ---------------------------------------------------------------------------
// Fused two-tower scorer, round 9: fp16 m16n8k16, 1024 threads (32 warps,
// 8 warps/SMSP) to attack the latency bound. Tile 128x256, warp tile 16x64,
// acc 32 regs/thread, <=64 regs total for full-RF occupancy of 50%.
// KC=32: one LDS.128 per row covers both k-steps (pos = 4t + 2s + b layout).
// ---------------------------------------------------------------------------

#define NTHREADS 1024
#define TB       128     // batch rows per CTA
#define LOUT     256     // latents (GEMM N)
#define KF       512     // features (GEMM K)
#define KC       32      // K chunk (elements) = 16 fp16 pairs per row
#define NCHUNK   32      // 16 chunks per tower x 2 towers
#define ASTU     16      // A smem row stride (uints) == 16 mod 32: conflict-free
#define WSTU     16      // W smem row stride (uints)
#define ULST     264     // user-latent smem stride (halves)

// smem byte offsets
#define S_IDXU   0                       // 128 ints
#define S_IDXI   512
#define S_UB     1024                    // 256 f32
#define S_IB     2048
#define S_PART   3072                    // 128 f32
#define S_ULAT   3584                    // 128 x 264 half = 67584
#define S_A      71168                   // A tiles, double buffered
#define A_BYTES  (TB * ASTU * 4)         // 8192
#define S_W      (S_A + 2 * A_BYTES)     // 87552, W triple buffered
#define W_BYTES  (LOUT * WSTU * 4)       // 16384
#define S_TOTAL  (S_W + 3 * W_BYTES)     // 136704

// pre-converted, permuted fp16 weights, per-chunk contiguous:
// index = tower*65536 + ch*4096 + l*16 + pos;  pos = 4t + 2s + b for
// pair p = 8s + 4b + t  (k = ch*32 + 2p, 2p+1)
__device__ uint32_t wscr[2 * 16 * LOUT * 16];

// --------------------------- helpers ----------------------------------------

__device__ __forceinline__ void mma16(float* c, uint32_t a0, uint32_t a1,
                                      uint32_t a2, uint32_t a3,
                                      uint32_t b0, uint32_t b1) {
    asm volatile(
        "mma.sync.aligned.m16n8k16.row.col.f32.f16.f16.f32 "
        "{%0,%1,%2,%3}, {%4,%5,%6,%7}, {%8,%9}, {%0,%1,%2,%3};"
        : "+f"(c[0]), "+f"(c[1]), "+f"(c[2]), "+f"(c[3])
        : "r"(a0), "r"(a1), "r"(a2), "r"(a3), "r"(b0), "r"(b1));
}

__device__ __forceinline__ void cp16(uint32_t dst, const void* src) {
    asm volatile("cp.async.cg.shared.global [%0], [%1], 16;"
                 :: "r"(dst), "l"(src) : "memory");
}

__device__ __forceinline__ uint32_t h2u(__half2 h) {
    return *reinterpret_cast<uint32_t*>(&h);
}

// pos(p) = 4*(p&3) + 2*(p>>3) + ((p>>2)&1)
__device__ __forceinline__ int posof(int p) {
    return ((p & 3) << 2) | ((p >> 3) << 1) | ((p >> 2) & 1);
}

// W chunk c -> smem buffer c%3 (scratch already fp16 + permuted)
__device__ __forceinline__ void issue_w(int c, uint32_t sb, int tid) {
    const int tower = c >> 4, ch = c & 15, buf = c % 3;
    const uint32_t* src0 = wscr + tower * 65536 + ch * 4096;
    const uint32_t dst0 = sb + S_W + buf * W_BYTES;
    // 256 rows x 4 x 16B = 1024 segs / 1024 thr
    int row = tid >> 2, q = tid & 3;
    cp16(dst0 + row * (WSTU * 4) + q * 16, src0 + row * WSTU + q * 4);
    asm volatile("cp.async.commit_group;" ::: "memory");
}

// A chunk: 128 rows x 8 float4 = 1024 segs / 1024 thr
__device__ __forceinline__ void ldg_a(float4* pref, const float* lut,
                                      const int* idx, int kc, int tid) {
    int row = tid >> 3, q = tid & 7;
    *pref = __ldg(reinterpret_cast<const float4*>(
        lut + (size_t)idx[row] * KF + kc + q * 4));
}

// store A chunk as fp16 pairs with permutation
__device__ __forceinline__ void sts_a(const float4* pref, char* smem, int c,
                                      int tid) {
    uint32_t* base = (uint32_t*)(smem + S_A + (c & 1) * A_BYTES);
    int row = tid >> 3, q = tid & 7;
    int p1 = 2 * q, p2 = 2 * q + 1;
    base[row * ASTU + posof(p1)] = h2u(__floats2half2_rn(pref->x, pref->y));
    base[row * ASTU + posof(p2)] = h2u(__floats2half2_rn(pref->z, pref->w));
}

// --------------------------- prep kernel ------------------------------------

__global__ void prep_kernel(const float* __restrict__ uW,
                            const float* __restrict__ iW) {
    int o = blockIdx.x * 256 + threadIdx.x;        // [0, 131072)
    int tower = o >> 16;
    int r = o & 65535;
    int ch = r >> 12;
    int l = (r >> 4) & (LOUT - 1);
    int pos = r & 15;
    int t = pos >> 2, s = (pos >> 1) & 1, b = pos & 1;
    int p = 8 * s + 4 * b + t;
    const float* W = (tower ? iW : uW) + (size_t)l * KF + ch * KC + 2 * p;
    wscr[o] = h2u(__floats2half2_rn(W[0], W[1]));
}

// --------------------------- main kernel ------------------------------------

__global__ void __launch_bounds__(NTHREADS, 1) towers_kernel(
    const int* __restrict__ x,
    const float* __restrict__ ulut, const float* __restrict__ ilut,
    const float* __restrict__ ubias, const float* __restrict__ ibias,
    float* __restrict__ out) {
    extern __shared__ char smem[];
    uint32_t sb;
    asm("{ .reg .u64 t; cvta.to.shared.u64 t, %1; cvt.u32.u64 %0, t; }"
        : "=r"(sb) : "l"(smem));
    const int tid  = threadIdx.x;
    const int lane = tid & 31;
    const int wid  = tid >> 5;
    const int wm   = wid & 7;        // 8 row groups of 16
    const int wn   = wid >> 3;       // 4 col groups of 64
    const int g    = lane >> 2;
    const int t    = lane & 3;

    int*   idxu = (int*)(smem + S_IDXU);
    int*   idxi = (int*)(smem + S_IDXI);
    float* ubS  = (float*)(smem + S_UB);
    float* ibS  = (float*)(smem + S_IB);
    float* part = (float*)(smem + S_PART);
    __half* ulat = (__half*)(smem + S_ULAT);

    if (tid < LOUT) {
        ubS[tid] = ubias[tid];
        ibS[tid] = ibias[tid];
    }
    if (tid < TB) {
        part[tid] = 0.f;
        int gg = blockIdx.x * TB + tid;
        idxu[tid] = x[2 * gg];
        idxi[tid] = x[2 * gg + 1];
    }
    __syncthreads();

    issue_w(0, sb, tid);
    issue_w(1, sb, tid);

    float4 pref;
    ldg_a(&pref, ulut, idxu, 0, tid);

    float acc[8][4];
#pragma unroll
    for (int nt = 0; nt < 8; nt++)
#pragma unroll
        for (int i = 0; i < 4; i++) acc[nt][i] = 0.f;

    const int rlo = wm * 16 + g;         // fragment rows
    const int rhi = wm * 16 + 8 + g;

    for (int c = 0; c < NCHUNK; c++) {
        // 1. store prefetched A; buffer (c&1)'s last reader MMA(c-2) is
        //    CTA-wide complete past sync(c-1).
        sts_a(&pref, smem, c, tid);

        // 2. prefetch next A chunk
        if (c + 1 < NCHUNK) {
            int c2 = c + 1;
            bool t2 = (c2 >= NCHUNK / 2);
            ldg_a(&pref, t2 ? ilut : ulut, t2 ? idxi : idxu,
                  (c2 & 15) * KC, tid);
        }

        // 3. ensure W chunk c landed (newest outstanding group is c+1)
        if (c <= NCHUNK - 3)
            asm volatile("cp.async.wait_group 1;" ::: "memory");
        else
            asm volatile("cp.async.wait_group 0;" ::: "memory");
        __syncthreads();

        // 4. refill W pipeline
        if (c + 2 < NCHUNK) issue_w(c + 2, sb, tid);

        // 5. MMA on chunk c: 2 k-steps, one LDS.128 per row covers both
        const uint32_t* A  = (const uint32_t*)(smem + S_A + (c & 1) * A_BYTES);
        const uint32_t* Bs = (const uint32_t*)(smem + S_W + (c % 3) * W_BYTES);

        uint4 alo = *(const uint4*)(A + rlo * ASTU + 4 * t);
        uint4 ahi = *(const uint4*)(A + rhi * ASTU + 4 * t);
#pragma unroll
        for (int ntb = 0; ntb < 4; ntb++) {      // 2 n-tiles at a time
            uint4 bv0, bv1;
            {
                const int n0 = wn * 64 + (ntb * 2) * 8 + g;
                const int n1 = n0 + 8;
                bv0 = *(const uint4*)(Bs + n0 * WSTU + 4 * t);
                bv1 = *(const uint4*)(Bs + n1 * WSTU + 4 * t);
            }
            // kstep 0: x,y ; kstep 1: z,w
            mma16(acc[ntb * 2],     alo.x, ahi.x, alo.y, ahi.y, bv0.x, bv0.y);
            mma16(acc[ntb * 2 + 1], alo.x, ahi.x, alo.y, ahi.y, bv1.x, bv1.y);
            mma16(acc[ntb * 2],     alo.z, ahi.z, alo.w, ahi.w, bv0.z, bv0.w);
            mma16(acc[ntb * 2 + 1], alo.z, ahi.z, alo.w, ahi.w, bv1.z, bv1.w);
        }

        // 6. user-tower epilogue: bias + relu -> fp16 smem, reset acc
        if (c == NCHUNK / 2 - 1) {
#pragma unroll
            for (int nt = 0; nt < 8; nt++) {
                const int c0 = wn * 64 + nt * 8 + 2 * t;
                float u0 = fmaxf(acc[nt][0] + ubS[c0],     0.f);
                float u1 = fmaxf(acc[nt][1] + ubS[c0 + 1], 0.f);
                float u2 = fmaxf(acc[nt][2] + ubS[c0],     0.f);
                float u3 = fmaxf(acc[nt][3] + ubS[c0 + 1], 0.f);
                *(__half2*)(ulat + rlo * ULST + c0) = __floats2half2_rn(u0, u1);
                *(__half2*)(ulat + rhi * ULST + c0) = __floats2half2_rn(u2, u3);
                acc[nt][0] = acc[nt][1] = acc[nt][2] = acc[nt][3] = 0.f;
            }
        }
    }

    // item-tower epilogue: bias+relu, product with user latent, row-reduce
    {
        float s0 = 0.f, s1 = 0.f;
#pragma unroll
        for (int nt = 0; nt < 8; nt++) {
            const int c0 = wn * 64 + nt * 8 + 2 * t;
            float v0 = fmaxf(acc[nt][0] + ibS[c0],     0.f);
            float v1 = fmaxf(acc[nt][1] + ibS[c0 + 1], 0.f);
            float v2 = fmaxf(acc[nt][2] + ibS[c0],     0.f);
            float v3 = fmaxf(acc[nt][3] + ibS[c0 + 1], 0.f);
            float2 u01 = __half22float2(*(__half2*)(ulat + rlo * ULST + c0));
            float2 u23 = __half22float2(*(__half2*)(ulat + rhi * ULST + c0));
            s0 = fmaf(u01.x, v0, fmaf(u01.y, v1, s0));
            s1 = fmaf(u23.x, v2, fmaf(u23.y, v3, s1));
        }
        s0 += __shfl_xor_sync(0xffffffffu, s0, 1);
        s0 += __shfl_xor_sync(0xffffffffu, s0, 2);
        s1 += __shfl_xor_sync(0xffffffffu, s1, 1);
        s1 += __shfl_xor_sync(0xffffffffu, s1, 2);
        if (t == 0) {
            atomicAdd(&part[rlo], s0);
            atomicAdd(&part[rhi], s1);
        }
    }
    __syncthreads();

    if (tid < TB) out[blockIdx.x * TB + tid] = part[tid];
}

// --------------------------- launch -----------------------------------------

extern "C" void kernel_launch(void* const* d_in, const int* in_sizes, int n_in,
                              void* d_out, int out_size) {
    const int* x      = (const int*)d_in[0];
    const float* ulut = (const float*)d_in[1];
    const float* ilut = (const float*)d_in[2];
    const float* uW   = (const float*)d_in[3];
    const float* ub   = (const float*)d_in[4];
    const float* iW   = (const float*)d_in[5];
    const float* ib   = (const float*)d_in[6];
    float* out        = (float*)d_out;

    prep_kernel<<<2 * 16 * LOUT * 16 / 256, 256>>>(uW, iW);

    cudaFuncSetAttribute(towers_kernel,
                         cudaFuncAttributeMaxDynamicSharedMemorySize, S_TOTAL);
    int grid = out_size / TB;   // 16384 / 128 = 128
    towers_kernel<<<grid, NTHREADS, S_TOTAL>>>(x, ulut, ilut, ub, ib, out);
}

// round 10
// speedup vs baseline: 1.7283x; 1.0493x over previous
#include <cuda_runtime.h>
#include <cuda_fp16.h>
#include <cstdint>

// ---------------------------------------------------------------------------
// Fused two-tower scorer, round 10: R9 inner loop unchanged (fp16 m16n8k16,
// warp tile 16x64, KC=32, pos=4t+2s+b permuted layout), but CTA split in two:
// TB=64, 512 threads, 2 CTAs/SM (launch_bounds(512,2), 64-reg cap) so the
// two CTAs' LDS-burst / MMA phases interleave on the SM instead of the whole
// SM breathing in lockstep around one 32-warp barrier.
// ---------------------------------------------------------------------------

#define NTHREADS 512
#define TB       64      // batch rows per CTA
#define LOUT     256     // latents (GEMM N)
#define KF       512     // features (GEMM K)
#define KC       32      // K chunk (elements) = 16 fp16 pairs per row
#define NCHUNK   32      // 16 chunks per tower x 2 towers
#define ASTU     16      // A smem row stride (uints), conflict-free
#define WSTU     16      // W smem row stride (uints)
#define ULST     264     // user-latent smem stride (halves)

// smem byte offsets
#define S_IDXU   0                       // 64 ints
#define S_IDXI   256
#define S_UB     512                     // 256 f32
#define S_IB     1536
#define S_PART   2560                    // 64 f32
#define S_ULAT   3584                    // 64 x 264 half = 33792
#define S_A      37376                   // A tiles, double buffered
#define A_BYTES  (TB * ASTU * 4)         // 4096
#define S_W      (S_A + 2 * A_BYTES)     // 45568, W triple buffered
#define W_BYTES  (LOUT * WSTU * 4)       // 16384
#define S_TOTAL  (S_W + 3 * W_BYTES)     // 94720 -> 2 CTAs/SM

// pre-converted, permuted fp16 weights, per-chunk contiguous:
// index = tower*65536 + ch*4096 + l*16 + pos;  pos = 4t + 2s + b for
// pair p = 8s + 4b + t  (k = ch*32 + 2p, 2p+1)
__device__ uint32_t wscr[2 * 16 * LOUT * 16];

// --------------------------- helpers ----------------------------------------

__device__ __forceinline__ void mma16(float* c, uint32_t a0, uint32_t a1,
                                      uint32_t a2, uint32_t a3,
                                      uint32_t b0, uint32_t b1) {
    asm volatile(
        "mma.sync.aligned.m16n8k16.row.col.f32.f16.f16.f32 "
        "{%0,%1,%2,%3}, {%4,%5,%6,%7}, {%8,%9}, {%0,%1,%2,%3};"
        : "+f"(c[0]), "+f"(c[1]), "+f"(c[2]), "+f"(c[3])
        : "r"(a0), "r"(a1), "r"(a2), "r"(a3), "r"(b0), "r"(b1));
}

__device__ __forceinline__ void cp16(uint32_t dst, const void* src) {
    asm volatile("cp.async.cg.shared.global [%0], [%1], 16;"
                 :: "r"(dst), "l"(src) : "memory");
}

__device__ __forceinline__ uint32_t h2u(__half2 h) {
    return *reinterpret_cast<uint32_t*>(&h);
}

// pos(p) = 4*(p&3) + 2*(p>>3) + ((p>>2)&1)
__device__ __forceinline__ int posof(int p) {
    return ((p & 3) << 2) | ((p >> 3) << 1) | ((p >> 2) & 1);
}

// W chunk c -> smem buffer c%3 (scratch already fp16 + permuted)
__device__ __forceinline__ void issue_w(int c, uint32_t sb, int tid) {
    const int tower = c >> 4, ch = c & 15, buf = c % 3;
    const uint32_t* src0 = wscr + tower * 65536 + ch * 4096;
    const uint32_t dst0 = sb + S_W + buf * W_BYTES;
    // 256 rows x 4 x 16B = 1024 segs / 512 thr = 2 per thread
#pragma unroll
    for (int i = 0; i < 2; i++) {
        int seg = tid + i * NTHREADS;
        int row = seg >> 2, q = seg & 3;
        cp16(dst0 + row * (WSTU * 4) + q * 16, src0 + row * WSTU + q * 4);
    }
    asm volatile("cp.async.commit_group;" ::: "memory");
}

// A chunk: 64 rows x 8 float4 = 512 segs / 512 thr
__device__ __forceinline__ void ldg_a(float4* pref, const float* lut,
                                      const int* idx, int kc, int tid) {
    int row = tid >> 3, q = tid & 7;
    *pref = __ldg(reinterpret_cast<const float4*>(
        lut + (size_t)idx[row] * KF + kc + q * 4));
}

// store A chunk as fp16 pairs with permutation
__device__ __forceinline__ void sts_a(const float4* pref, char* smem, int c,
                                      int tid) {
    uint32_t* base = (uint32_t*)(smem + S_A + (c & 1) * A_BYTES);
    int row = tid >> 3, q = tid & 7;
    int p1 = 2 * q, p2 = 2 * q + 1;
    base[row * ASTU + posof(p1)] = h2u(__floats2half2_rn(pref->x, pref->y));
    base[row * ASTU + posof(p2)] = h2u(__floats2half2_rn(pref->z, pref->w));
}

// --------------------------- prep kernel ------------------------------------

__global__ void prep_kernel(const float* __restrict__ uW,
                            const float* __restrict__ iW) {
    int o = blockIdx.x * 256 + threadIdx.x;        // [0, 131072)
    int tower = o >> 16;
    int r = o & 65535;
    int ch = r >> 12;
    int l = (r >> 4) & (LOUT - 1);
    int pos = r & 15;
    int t = pos >> 2, s = (pos >> 1) & 1, b = pos & 1;
    int p = 8 * s + 4 * b + t;
    const float* W = (tower ? iW : uW) + (size_t)l * KF + ch * KC + 2 * p;
    wscr[o] = h2u(__floats2half2_rn(W[0], W[1]));
}

// --------------------------- main kernel ------------------------------------

__global__ void __launch_bounds__(NTHREADS, 2) towers_kernel(
    const int* __restrict__ x,
    const float* __restrict__ ulut, const float* __restrict__ ilut,
    const float* __restrict__ ubias, const float* __restrict__ ibias,
    float* __restrict__ out) {
    extern __shared__ char smem[];
    uint32_t sb;
    asm("{ .reg .u64 t; cvta.to.shared.u64 t, %1; cvt.u32.u64 %0, t; }"
        : "=r"(sb) : "l"(smem));
    const int tid  = threadIdx.x;
    const int lane = tid & 31;
    const int wid  = tid >> 5;
    const int wm   = wid & 3;        // 4 row groups of 16
    const int wn   = wid >> 2;       // 4 col groups of 64
    const int g    = lane >> 2;
    const int t    = lane & 3;

    int*   idxu = (int*)(smem + S_IDXU);
    int*   idxi = (int*)(smem + S_IDXI);
    float* ubS  = (float*)(smem + S_UB);
    float* ibS  = (float*)(smem + S_IB);
    float* part = (float*)(smem + S_PART);
    __half* ulat = (__half*)(smem + S_ULAT);

    if (tid < LOUT) {
        ubS[tid] = ubias[tid];
        ibS[tid] = ibias[tid];
    }
    if (tid < TB) {
        part[tid] = 0.f;
        int gg = blockIdx.x * TB + tid;
        idxu[tid] = x[2 * gg];
        idxi[tid] = x[2 * gg + 1];
    }
    __syncthreads();

    issue_w(0, sb, tid);
    issue_w(1, sb, tid);

    float4 pref;
    ldg_a(&pref, ulut, idxu, 0, tid);

    float acc[8][4];
#pragma unroll
    for (int nt = 0; nt < 8; nt++)
#pragma unroll
        for (int i = 0; i < 4; i++) acc[nt][i] = 0.f;

    const int rlo = wm * 16 + g;         // fragment rows
    const int rhi = wm * 16 + 8 + g;

    for (int c = 0; c < NCHUNK; c++) {
        // 1. store prefetched A; buffer (c&1)'s last reader MMA(c-2) is
        //    CTA-wide complete past sync(c-1).
        sts_a(&pref, smem, c, tid);

        // 2. prefetch next A chunk
        if (c + 1 < NCHUNK) {
            int c2 = c + 1;
            bool t2 = (c2 >= NCHUNK / 2);
            ldg_a(&pref, t2 ? ilut : ulut, t2 ? idxi : idxu,
                  (c2 & 15) * KC, tid);
        }

        // 3. ensure W chunk c landed (newest outstanding group is c+1)
        if (c <= NCHUNK - 3)
            asm volatile("cp.async.wait_group 1;" ::: "memory");
        else
            asm volatile("cp.async.wait_group 0;" ::: "memory");
        __syncthreads();

        // 4. refill W pipeline
        if (c + 2 < NCHUNK) issue_w(c + 2, sb, tid);

        // 5. MMA on chunk c: 2 k-steps, one LDS.128 per row covers both
        const uint32_t* A  = (const uint32_t*)(smem + S_A + (c & 1) * A_BYTES);
        const uint32_t* Bs = (const uint32_t*)(smem + S_W + (c % 3) * W_BYTES);

        uint4 alo = *(const uint4*)(A + rlo * ASTU + 4 * t);
        uint4 ahi = *(const uint4*)(A + rhi * ASTU + 4 * t);
#pragma unroll
        for (int ntb = 0; ntb < 4; ntb++) {      // 2 n-tiles at a time
            uint4 bv0, bv1;
            {
                const int n0 = wn * 64 + (ntb * 2) * 8 + g;
                const int n1 = n0 + 8;
                bv0 = *(const uint4*)(Bs + n0 * WSTU + 4 * t);
                bv1 = *(const uint4*)(Bs + n1 * WSTU + 4 * t);
            }
            // kstep 0: x,y ; kstep 1: z,w
            mma16(acc[ntb * 2],     alo.x, ahi.x, alo.y, ahi.y, bv0.x, bv0.y);
            mma16(acc[ntb * 2 + 1], alo.x, ahi.x, alo.y, ahi.y, bv1.x, bv1.y);
            mma16(acc[ntb * 2],     alo.z, ahi.z, alo.w, ahi.w, bv0.z, bv0.w);
            mma16(acc[ntb * 2 + 1], alo.z, ahi.z, alo.w, ahi.w, bv1.z, bv1.w);
        }

        // 6. user-tower epilogue: bias + relu -> fp16 smem, reset acc
        if (c == NCHUNK / 2 - 1) {
#pragma unroll
            for (int nt = 0; nt < 8; nt++) {
                const int c0 = wn * 64 + nt * 8 + 2 * t;
                float u0 = fmaxf(acc[nt][0] + ubS[c0],     0.f);
                float u1 = fmaxf(acc[nt][1] + ubS[c0 + 1], 0.f);
                float u2 = fmaxf(acc[nt][2] + ubS[c0],     0.f);
                float u3 = fmaxf(acc[nt][3] + ubS[c0 + 1], 0.f);
                *(__half2*)(ulat + rlo * ULST + c0) = __floats2half2_rn(u0, u1);
                *(__half2*)(ulat + rhi * ULST + c0) = __floats2half2_rn(u2, u3);
                acc[nt][0] = acc[nt][1] = acc[nt][2] = acc[nt][3] = 0.f;
            }
        }
    }

    // item-tower epilogue: bias+relu, product with user latent, row-reduce
    {
        float s0 = 0.f, s1 = 0.f;
#pragma unroll
        for (int nt = 0; nt < 8; nt++) {
            const int c0 = wn * 64 + nt * 8 + 2 * t;
            float v0 = fmaxf(acc[nt][0] + ibS[c0],     0.f);
            float v1 = fmaxf(acc[nt][1] + ibS[c0 + 1], 0.f);
            float v2 = fmaxf(acc[nt][2] + ibS[c0],     0.f);
            float v3 = fmaxf(acc[nt][3] + ibS[c0 + 1], 0.f);
            float2 u01 = __half22float2(*(__half2*)(ulat + rlo * ULST + c0));
            float2 u23 = __half22float2(*(__half2*)(ulat + rhi * ULST + c0));
            s0 = fmaf(u01.x, v0, fmaf(u01.y, v1, s0));
            s1 = fmaf(u23.x, v2, fmaf(u23.y, v3, s1));
        }
        s0 += __shfl_xor_sync(0xffffffffu, s0, 1);
        s0 += __shfl_xor_sync(0xffffffffu, s0, 2);
        s1 += __shfl_xor_sync(0xffffffffu, s1, 1);
        s1 += __shfl_xor_sync(0xffffffffu, s1, 2);
        if (t == 0) {
            atomicAdd(&part[rlo], s0);
            atomicAdd(&part[rhi], s1);
        }
    }
    __syncthreads();

    if (tid < TB) out[blockIdx.x * TB + tid] = part[tid];
}

// --------------------------- launch -----------------------------------------

extern "C" void kernel_launch(void* const* d_in, const int* in_sizes, int n_in,
                              void* d_out, int out_size) {
    const int* x      = (const int*)d_in[0];
    const float* ulut = (const float*)d_in[1];
    const float* ilut = (const float*)d_in[2];
    const float* uW   = (const float*)d_in[3];
    const float* ub   = (const float*)d_in[4];
    const float* iW   = (const float*)d_in[5];
    const float* ib   = (const float*)d_in[6];
    float* out        = (float*)d_out;

    prep_kernel<<<2 * 16 * LOUT * 16 / 256, 256>>>(uW, iW);

    cudaFuncSetAttribute(towers_kernel,
                         cudaFuncAttributeMaxDynamicSharedMemorySize, S_TOTAL);
    int grid = out_size / TB;   // 16384 / 64 = 256
    towers_kernel<<<grid, NTHREADS, S_TOTAL>>>(x, ulut, ilut, ub, ib, out);
}